// round 12
// baseline (speedup 1.0000x reference)
#include <cuda_runtime.h>

#define B 8
#define A 65536
#define C 80
#define G 16
#define TOPK 50
#define NB 4096
#define BSH 18
#define CANDC 4096
#define CAP 65536
#define KA_BLOCKS 2048
#define KN_BLOCKS 6144
#define KD_BLOCKS 256

typedef unsigned long long u64;

// ------------------------- static device scratch -------------------------
__device__ unsigned g_maxiou[B * G];             // max decoded IoU (bits)
__device__ int      g_lcnt[B * G];               // sparse mqm list counts
__device__ u64      g_list[(size_t)B * G * CAP]; // sparse mqm keys (bits<<32 | ~a)
__device__ int      g_nrec;                      // sparse record count
__device__ unsigned g_rec[B * A];                // sparse records (b<<16 | a)
__device__ double   g_sums[2];                   // [0]=pos, [1]=neg

// ------------------------------ helpers ---------------------------------
// _rn-pinned ops: all IoU computations are bitwise identical across call sites.
struct Corners { float x0, y0, x1, y1, area; };

__device__ __forceinline__ Corners corners_rn(const float4 p) {
    Corners c;
    c.x0 = __fmaf_rn(-0.5f, p.z, p.x);
    c.y0 = __fmaf_rn(-0.5f, p.w, p.y);
    c.x1 = __fmaf_rn( 0.5f, p.z, p.x);
    c.y1 = __fmaf_rn( 0.5f, p.w, p.y);
    c.area = __fmul_rn(p.z, p.w);
    return c;
}

__device__ __forceinline__ float iou_ct(const Corners c, const float4 t, float tA) {
    float iw = fmaxf(__fsub_rn(fminf(c.x1, t.z), fmaxf(c.x0, t.x)), 0.f);
    float ih = fmaxf(__fsub_rn(fminf(c.y1, t.w), fmaxf(c.y0, t.y)), 0.f);
    float inter = __fmul_rn(iw, ih);
    if (inter <= 0.f) return 0.f;
    return __fdividef(inter, __fsub_rn(__fadd_rn(tA, c.area), inter));
}

__device__ __forceinline__ float fiou_rn(const float4 t, float tA,
                                         float bx0, float by0, float bx1, float by1, float bA) {
    float iw = fmaxf(__fsub_rn(fminf(t.z, bx1), fmaxf(t.x, bx0)), 0.f);
    float ih = fmaxf(__fsub_rn(fminf(t.w, by1), fmaxf(t.y, by0)), 0.f);
    float inter = __fmul_rn(iw, ih);
    if (inter <= 0.f) return 0.f;
    return __fdividef(inter, __fsub_rn(__fadd_rn(tA, bA), inter));
}

__device__ __forceinline__ float fastrcp(float s) {
    float r = __uint_as_float(0x7EF311C3u - __float_as_uint(s));
    r = r * (2.f - s * r);
    r = r * (2.f - s * r);
    r = r * (2.f - s * r);
    return r;
}

// sigmoid(x)^2 * softplus(x): 2 MUFU (EX2 + LG2)
__device__ __forceinline__ float negterm(float x) {
    float e = __expf(x);
    float s = 1.f + e;
    float p = e * fastrcp(s);
    return p * p * __logf(s);
}

__device__ __forceinline__ float sl1(float v) {
    float av = fabsf(v);
    return (av < 0.11f) ? 4.5454545454545450f * v * v : av - 0.055f;
}

__device__ __forceinline__ float blockReduceSum(float v) {
    __shared__ float s[32];
    int lane = threadIdx.x & 31, wid = threadIdx.x >> 5;
    #pragma unroll
    for (int o = 16; o; o >>= 1) v += __shfl_down_sync(0xffffffffu, v, o);
    if (lane == 0) s[wid] = v;
    __syncthreads();
    int nw = (blockDim.x + 31) >> 5;
    v = (threadIdx.x < nw) ? s[threadIdx.x] : 0.f;
    if (wid == 0) {
        #pragma unroll
        for (int o = 16; o; o >>= 1) v += __shfl_down_sync(0xffffffffu, v, o);
    }
    return v; // valid in thread 0
}

// ------------------------------ kernels ---------------------------------
__global__ void kI() {
    int i = threadIdx.x;
    if (i < B * G) { g_maxiou[i] = 0u; g_lcnt[i] = 0; }
    if (i == 0) { g_sums[0] = 0.0; g_sums[1] = 0.0; g_nrec = 0; }
}

// Fused: blocks [0,KA_BLOCKS) = per-anchor pass: mqm sparse push + decoded-IoU
//        t2 max + sparse records; rest = dense negative loss over logits.
__global__ void kAN(const float4* __restrict__ br, const float4* __restrict__ anc,
                    const float4* __restrict__ tbx, const float4* __restrict__ logits4) {
    int tid = threadIdx.x;
    if (blockIdx.x < KA_BLOCKS) {
        int b = blockIdx.x >> 8;
        int a = ((blockIdx.x & 255) << 8) | tid;
        int lane = tid & 31;
        __shared__ float4 st[G];
        __shared__ float  sta[G];
        __shared__ unsigned smax[G];
        if (tid < G) {
            float4 t = tbx[b * G + tid];
            st[tid] = t;
            sta[tid] = __fmul_rn(__fsub_rn(t.z, t.x), __fsub_rn(t.w, t.y));
            smax[tid] = 0u;
        }
        __syncthreads();

        float4 l = br[b * A + a];
        float4 p = anc[a];
        Corners ac = corners_rn(p);
        float dcx = p.x + l.x * 0.1f * p.z;
        float dcy = p.y + l.y * 0.1f * p.w;
        float dw  = p.z * __expf(l.z * 0.2f);
        float dh  = p.w * __expf(l.w * 0.2f);
        float dx0 = dcx - 0.5f * dw, dy0 = dcy - 0.5f * dh;
        float dx1 = dcx + 0.5f * dw, dy1 = dcy + 0.5f * dh;
        float dA  = dw * dh;

        float dmax = 0.f;
        #pragma unroll
        for (int g = 0; g < G; g++) {
            float4 t = st[g];
            float tA = sta[g];
            // mqm IoU: sparse push (warp-aggregated) — the ONLY place it's computed
            float mi = iou_ct(ac, t, tA);
            bool push = (mi > 0.f);
            unsigned mask = __ballot_sync(0xffffffffu, push);
            if (push) {
                int bg = b * G + g;
                int leader = __ffs(mask) - 1;
                int rank = __popc(mask & ((1u << lane) - 1u));
                int base = 0;
                if (lane == leader) base = atomicAdd(&g_lcnt[bg], __popc(mask));
                base = __shfl_sync(mask, base, leader);
                g_list[(size_t)bg * CAP + base + rank] =
                    ((u64)__float_as_uint(mi) << 32) | (unsigned)(~(unsigned)a);
            }
            // decoded IoU: t2 max
            float di = fiou_rn(t, tA, dx0, dy0, dx1, dy1, dA);
            dmax = fmaxf(dmax, di);
            unsigned db = __float_as_uint(di);
            if (db > smax[g]) atomicMax(&smax[g], db);   // read-filtered max
        }
        if (dmax > 0.49f) {                              // margin vs recompute drift
            int pos = atomicAdd(&g_nrec, 1);
            g_rec[pos] = ((unsigned)b << 16) | (unsigned)a;
        }
        __syncthreads();
        if (tid < G) atomicMax(&g_maxiou[b * G + tid], smax[tid]);
    } else {
        const int n4 = B * A * C / 4;
        int bid = blockIdx.x - KA_BLOCKS;
        float acc = 0.f;
        for (int i = bid * 256 + tid; i < n4; i += KN_BLOCKS * 256) {
            float4 v = logits4[i];
            acc += negterm(v.x) + negterm(v.y) + negterm(v.z) + negterm(v.w);
        }
        float tot = blockReduceSum(acc);
        if (tid == 0) atomicAdd(&g_sums[1], (double)tot);
    }
}

// One block per (b,g): local hist of sparse list -> threshold -> filter ->
// exact top-50 rank -> positive bag loss. No IoU recomputation.
__global__ void kS(const float4* __restrict__ br, const float4* __restrict__ anc,
                   const float4* __restrict__ tbx, const int* __restrict__ lab,
                   const float* __restrict__ logits) {
    __shared__ unsigned hist[NB];
    __shared__ u64 cand[CANDC];
    __shared__ unsigned sp[256];
    __shared__ unsigned ssel[TOPK];
    __shared__ float swv[TOPK], swl[TOPK];
    __shared__ int scc, scount, stbin;
    __shared__ unsigned sflags[256];

    int tid = threadIdx.x;
    int bg = blockIdx.x;
    int b = bg >> 4;
    float4 t = tbx[bg];
    float tA = __fmul_rn(__fsub_rn(t.z, t.x), __fsub_rn(t.w, t.y));
    int cnt = g_lcnt[bg];                 // <= CAP by construction
    const u64* lst = g_list + (size_t)bg * CAP;

    for (int i = tid; i < NB; i += 256) hist[i] = 0u;
    if (tid == 0) { scc = 0; scount = 0; stbin = 0; }
    __syncthreads();

    // local histogram of stored IoU bits
    for (int i = tid; i < cnt; i += 256)
        atomicAdd(&hist[(unsigned)(lst[i] >> 32) >> BSH], 1u);
    __syncthreads();

    // threshold bin: largest suffix with count >= TOPK
    unsigned accp = 0;
    #pragma unroll
    for (int i = 0; i < NB / 256; i++) accp += hist[tid * (NB / 256) + i];
    sp[tid] = accp;
    __syncthreads();
    if (tid == 0) {
        int cum = 0, tb = 0;
        for (int c = 255; c >= 0; c--) {
            if (cum + (int)sp[c] >= TOPK) {
                int base = c * (NB / 256);
                for (int i = NB / 256 - 1; i >= 0; i--) {
                    cum += (int)hist[base + i];
                    if (cum >= TOPK) { tb = base + i; break; }
                }
                break;
            }
            cum += (int)sp[c];
        }
        stbin = tb;
    }
    __syncthreads();
    u64 thrkey = ((u64)((unsigned)stbin << BSH)) << 32;

    // filter candidates (>= threshold bin) into smem
    for (int i = tid; i < cnt; i += 256) {
        u64 k = lst[i];
        if (k >= thrkey) {
            int pos = atomicAdd(&scc, 1);
            if (pos < CANDC) cand[pos] = k;
        }
    }
    __syncthreads();
    int cc = min(scc, CANDC);

    // exact rank top-50 (value desc, index asc)
    for (int i = tid; i < cc; i += 256) {
        u64 k = cand[i];
        int r = 0;
        for (int j = 0; j < cc; j++) r += (cand[j] > k);
        if (r < TOPK) {
            int s = atomicAdd(&scount, 1);
            ssel[s] = ~(unsigned)(k & 0xffffffffu);
        }
    }
    __syncthreads();

    // deficit (rare): fewer than 50 positive-IoU anchors -> zero-IoU anchors, idx asc
    if (scount < TOPK) {
        for (int base = 0; base < A && scount < TOPK; base += 256) {
            Corners ac = corners_rn(anc[base + tid]);
            float mi = iou_ct(ac, t, tA);
            sflags[tid] = (mi <= 0.f);
            __syncthreads();
            if (tid == 0) {
                for (int j = 0; j < 256 && scount < TOPK; j++)
                    if (sflags[j]) ssel[scount++] = (unsigned)(base + j);
            }
            __syncthreads();
        }
    }
    int n = scount;

    // positive bag loss epilogue
    if (tid < n) {
        unsigned a = ssel[tid];
        float4 p = anc[a];
        float4 l = br[(size_t)b * A + a];
        int lbl = lab[bg];
        float xl = logits[((size_t)(b * A) + a) * C + lbl];
        float e = __expf(xl);
        float mcp = __fdividef(e, 1.f + e);
        float gx = __fdividef((t.x + t.z) * 0.5f - p.x, 0.1f * p.z);
        float gy = __fdividef((t.y + t.w) * 0.5f - p.y, 0.1f * p.w);
        float gw = __logf(__fdividef(t.z - t.x, p.z)) * 5.0f;
        float gh = __logf(__fdividef(t.w - t.y, p.w)) * 5.0f;
        float reg = 0.75f * (sl1(gx - l.x) + sl1(gy - l.y) + sl1(gw - l.z) + sl1(gh - l.w));
        float mbp = __expf(-reg);
        float li = mcp * mbp;
        float w = __fdividef(1.f, fmaxf(1.f - li, 1e-12f));
        swv[tid] = w;
        swl[tid] = w * li;
    }
    __syncthreads();
    if (tid == 0 && n > 0) {
        float sw = 0.f, sl = 0.f;
        for (int i = 0; i < n; i++) { sw += swv[i]; sl += swl[i]; }
        float bag = __fdividef(sl, sw);
        atomicAdd(&g_sums[0], (double)(-__logf(bag)));
    }
}

// Sparse negative-loss correction (invden computed inline from g_maxiou)
__global__ void kD(const float4* __restrict__ br, const float4* __restrict__ anc,
                   const float4* __restrict__ tbx, const int* __restrict__ lab,
                   const float* __restrict__ logits) {
    __shared__ float4 st[B * G];
    __shared__ float  sta[B * G];
    __shared__ float  sinv[B * G];
    __shared__ int    slbl[B * G];
    __shared__ int    sfirst[B * G];
    if (threadIdx.x < B * G) {
        float4 t = tbx[threadIdx.x];
        st[threadIdx.x] = t;
        sta[threadIdx.x] = __fmul_rn(__fsub_rn(t.z, t.x), __fsub_rn(t.w, t.y));
        slbl[threadIdx.x] = lab[threadIdx.x];
        float m = __uint_as_float(g_maxiou[threadIdx.x]);
        sinv[threadIdx.x] = (m > 0.5f) ? __fdividef(1.f, m - 0.5f) : 0.f;
    }
    __syncthreads();
    if (threadIdx.x < B * G) {
        int b = threadIdx.x >> 4, g = threadIdx.x & 15, f = 1;
        for (int j = 0; j < g; j++) if (slbl[b * G + j] == slbl[threadIdx.x]) f = 0;
        sfirst[threadIdx.x] = f;
    }
    __syncthreads();

    int nrec = g_nrec;
    float corr = 0.f;
    for (int i = blockIdx.x * blockDim.x + threadIdx.x; i < nrec; i += KD_BLOCKS * blockDim.x) {
        unsigned rec = g_rec[i];
        int b = rec >> 16;
        int a = rec & 0xffff;
        float4 l = br[b * A + a];
        float4 p = anc[a];
        float dcx = p.x + l.x * 0.1f * p.z;
        float dcy = p.y + l.y * 0.1f * p.w;
        float dw  = p.z * __expf(l.z * 0.2f);
        float dh  = p.w * __expf(l.w * 0.2f);
        float dx0 = dcx - 0.5f * dw, dy0 = dcy - 0.5f * dh;
        float dx1 = dcx + 0.5f * dw, dy1 = dcy + 0.5f * dh;
        float dA  = dw * dh;
        float obp[G];
        #pragma unroll
        for (int g = 0; g < G; g++) {
            int bg = b * G + g;
            float di = fiou_rn(st[bg], sta[bg], dx0, dy0, dx1, dy1, dA);
            obp[g] = fminf(fmaxf((di - 0.5f) * sinv[bg], 0.f), 1.f);
        }
        #pragma unroll
        for (int g = 0; g < G; g++) {
            int bg = b * G + g;
            if (!sfirst[bg]) continue;
            float bp = obp[g];
            #pragma unroll
            for (int j = g + 1; j < G; j++)
                if (slbl[b * G + j] == slbl[bg]) bp = fmaxf(bp, obp[j]);
            if (bp > 0.f) {
                float xl = logits[((size_t)(b * A) + a) * C + slbl[bg]];
                float pt = negterm(xl);               // cancels dense term exactly
                float e = __expf(xl);
                float pp = e * fastrcp(1.f + e);
                float x = pp * (1.f - bp);
                float xt = x * x * (-__logf(1.f - x));
                corr += xt - pt;
            }
        }
    }
    float tot = blockReduceSum(corr);
    if (threadIdx.x == 0 && tot != 0.f) atomicAdd(&g_sums[1], (double)tot);
}

__global__ void kF(float* out) {
    out[0] = (float)(g_sums[0] * (0.5 / 128.0));    // ALPHA / (B*G)
    out[1] = (float)(g_sums[1] * (0.5 / 6400.0));   // (1-ALPHA) / (B*G*TOPK)
}

// ------------------------------ launch -----------------------------------
extern "C" void kernel_launch(void* const* d_in, const int* in_sizes, int n_in,
                              void* d_out, int out_size) {
    const float4* br     = (const float4*)d_in[0];   // box_regression (B,A,4)
    const float*  logits = (const float*) d_in[1];   // cls_logits (B,A,C)
    const float4* anc    = (const float4*)d_in[2];   // anchors (A,4)
    const float4* tbx    = (const float4*)d_in[3];   // targets_boxes (B,G,4)
    const int*    lab    = (const int*)   d_in[4];   // labels (B,G)
    float* out = (float*)d_out;

    kI<<<1, 128>>>();
    kAN<<<KA_BLOCKS + KN_BLOCKS, 256>>>(br, anc, tbx, (const float4*)logits);
    kS<<<B * G, 256>>>(br, anc, tbx, lab, logits);
    kD<<<KD_BLOCKS, 256>>>(br, anc, tbx, lab, logits);
    kF<<<1, 1>>>(out);
}

// round 13
// speedup vs baseline: 2.1707x; 2.1707x over previous
#include <cuda_runtime.h>

#define B 8
#define A 65536
#define C 80
#define G 16
#define TOPK 50
#define NBINS 8192
#define BSHIFT 17
#define CAND 4096
#define KA_BLOCKS 2048
#define KN_BLOCKS 6144
#define KD_CAND_BLOCKS 2048
#define KD_SP_BLOCKS 256

// ------------------------- static device scratch -------------------------
__device__ unsigned g_hist[(size_t)B * G * NBINS];   // 4.2 MB histograms
__device__ unsigned g_maxiou[B * G];                 // max decoded IoU (bits)
__device__ unsigned g_thr[B * G];                    // threshold float bits (tbin<<17)
__device__ float    g_invden[B * G];                 // 1/(t2-0.5) or 0
__device__ int      g_ccnt[B * G];                   // candidate counts
__device__ unsigned g_cand[(size_t)B * G * CAND];    // candidate anchor ids
__device__ int      g_nrec;                          // sparse record count
__device__ unsigned g_rec[B * A];                    // sparse records (b<<16 | a)
__device__ double   g_sums[2];                       // [0]=pos, [1]=neg

// ------------------------------ helpers ---------------------------------
// _rn-pinned ops: all IoU computations are bitwise identical across call sites.
struct Corners { float x0, y0, x1, y1, area; };

__device__ __forceinline__ Corners corners_rn(const float4 p) {
    Corners c;
    c.x0 = __fmaf_rn(-0.5f, p.z, p.x);
    c.y0 = __fmaf_rn(-0.5f, p.w, p.y);
    c.x1 = __fmaf_rn( 0.5f, p.z, p.x);
    c.y1 = __fmaf_rn( 0.5f, p.w, p.y);
    c.area = __fmul_rn(p.z, p.w);
    return c;
}

// Exact overlap precheck: true  <=>  iw > 0 && ih > 0  <=>  inter could be > 0.
// Uses the very same corner values as iou_ct, so it is exactly the inter<=0 gate.
__device__ __forceinline__ bool overlap_ct(const Corners c, const float4 t) {
    return (c.x0 < t.z) & (t.x < c.x1) & (c.y0 < t.w) & (t.y < c.y1);
}

__device__ __forceinline__ float iou_ct(const Corners c, const float4 t, float tA) {
    float iw = fmaxf(__fsub_rn(fminf(c.x1, t.z), fmaxf(c.x0, t.x)), 0.f);
    float ih = fmaxf(__fsub_rn(fminf(c.y1, t.w), fmaxf(c.y0, t.y)), 0.f);
    float inter = __fmul_rn(iw, ih);
    if (inter <= 0.f) return 0.f;
    return __fdividef(inter, __fsub_rn(__fadd_rn(tA, c.area), inter));
}

__device__ __forceinline__ float fiou_rn(const float4 t, float tA,
                                         float bx0, float by0, float bx1, float by1, float bA) {
    float iw = fmaxf(__fsub_rn(fminf(t.z, bx1), fmaxf(t.x, bx0)), 0.f);
    float ih = fmaxf(__fsub_rn(fminf(t.w, by1), fmaxf(t.y, by0)), 0.f);
    float inter = __fmul_rn(iw, ih);
    if (inter <= 0.f) return 0.f;
    return __fdividef(inter, __fsub_rn(__fadd_rn(tA, bA), inter));
}

__device__ __forceinline__ float fastrcp(float s) {
    float r = __uint_as_float(0x7EF311C3u - __float_as_uint(s));
    r = r * (2.f - s * r);
    r = r * (2.f - s * r);
    r = r * (2.f - s * r);
    return r;
}

// sigmoid(x)^2 * softplus(x): 2 MUFU (EX2 + LG2)
__device__ __forceinline__ float negterm(float x) {
    float e = __expf(x);
    float s = 1.f + e;
    float p = e * fastrcp(s);
    return p * p * __logf(s);
}

__device__ __forceinline__ float sl1(float v) {
    float av = fabsf(v);
    return (av < 0.11f) ? 4.5454545454545450f * v * v : av - 0.055f;
}

__device__ __forceinline__ float blockReduceSum(float v) {
    __shared__ float s[32];
    int lane = threadIdx.x & 31, wid = threadIdx.x >> 5;
    #pragma unroll
    for (int o = 16; o; o >>= 1) v += __shfl_down_sync(0xffffffffu, v, o);
    if (lane == 0) s[wid] = v;
    __syncthreads();
    int nw = (blockDim.x + 31) >> 5;
    v = (threadIdx.x < nw) ? s[threadIdx.x] : 0.f;
    if (wid == 0) {
        #pragma unroll
        for (int o = 16; o; o >>= 1) v += __shfl_down_sync(0xffffffffu, v, o);
    }
    return v; // valid in thread 0
}

// ------------------------------ kernels ---------------------------------
__global__ void kI() {
    size_t i = (size_t)blockIdx.x * blockDim.x + threadIdx.x;
    uint4* h4 = (uint4*)g_hist;
    const size_t n4 = (size_t)B * G * NBINS / 4;
    if (i < n4) h4[i] = make_uint4(0u, 0u, 0u, 0u);
    if (i < B * G) { g_maxiou[i] = 0u; g_ccnt[i] = 0; }
    if (i == 0) { g_sums[0] = 0.0; g_sums[1] = 0.0; g_nrec = 0; }
}

// Fused: blocks [0,KA_BLOCKS) = per-anchor pass (hist + t2 max + sparse records);
//        rest = dense negative loss over logits.
__global__ void kAN(const float4* __restrict__ br, const float4* __restrict__ anc,
                    const float4* __restrict__ tbx, const float4* __restrict__ logits4) {
    if (blockIdx.x < KA_BLOCKS) {
        int b = blockIdx.x >> 8;
        int a = ((blockIdx.x & 255) << 8) | threadIdx.x;
        __shared__ float4 st[G];
        __shared__ float  sta[G];
        __shared__ unsigned smax[G];
        if (threadIdx.x < G) {
            float4 t = tbx[b * G + threadIdx.x];
            st[threadIdx.x] = t;
            sta[threadIdx.x] = __fmul_rn(__fsub_rn(t.z, t.x), __fsub_rn(t.w, t.y));
            smax[threadIdx.x] = 0u;
        }
        __syncthreads();

        float4 l = br[b * A + a];
        float4 p = anc[a];
        Corners ac = corners_rn(p);              // hoisted: once per anchor
        float dcx = p.x + l.x * 0.1f * p.z;
        float dcy = p.y + l.y * 0.1f * p.w;
        float dw  = p.z * __expf(l.z * 0.2f);
        float dh  = p.w * __expf(l.w * 0.2f);
        float dx0 = dcx - 0.5f * dw, dy0 = dcy - 0.5f * dh;
        float dx1 = dcx + 0.5f * dw, dy1 = dcy + 0.5f * dh;
        float dA  = dw * dh;

        size_t hbase = (size_t)(b * G) * NBINS;
        float dmax = 0.f;
        #pragma unroll
        for (int g = 0; g < G; g++) {
            float4 t = st[g];
            // mqm IoU: exact separating-axis precheck skips ~85% of pairs
            if (overlap_ct(ac, t)) {
                float mi = iou_ct(ac, t, sta[g]);
                if (mi > 0.f)
                    atomicAdd(&g_hist[hbase + (size_t)g * NBINS + (__float_as_uint(mi) >> BSHIFT)], 1u);
            }
            // decoded IoU: same precheck (di=0 can't change dmax/smax)
            if ((dx0 < t.z) & (t.x < dx1) & (dy0 < t.w) & (t.y < dy1)) {
                float di = fiou_rn(t, sta[g], dx0, dy0, dx1, dy1, dA);
                dmax = fmaxf(dmax, di);
                unsigned db = __float_as_uint(di);
                if (db > smax[g]) atomicMax(&smax[g], db);   // read-filtered max
            }
        }
        if (dmax > 0.49f) {                      // margin vs recompute drift
            int pos = atomicAdd(&g_nrec, 1);
            g_rec[pos] = ((unsigned)b << 16) | (unsigned)a;
        }
        __syncthreads();
        if (threadIdx.x < G) atomicMax(&g_maxiou[b * G + threadIdx.x], smax[threadIdx.x]);
    } else {
        const int n4 = B * A * C / 4;
        int bid = blockIdx.x - KA_BLOCKS;
        float acc = 0.f;
        for (int i = bid * blockDim.x + threadIdx.x; i < n4; i += KN_BLOCKS * blockDim.x) {
            float4 v = logits4[i];
            acc += negterm(v.x) + negterm(v.y) + negterm(v.z) + negterm(v.w);
        }
        float tot = blockReduceSum(acc);
        if (threadIdx.x == 0) atomicAdd(&g_sums[1], (double)tot);
    }
}

// Threshold per (b,g): largest suffix bin with count >= TOPK; invden
__global__ void kT() {
    int bg = blockIdx.x;
    const unsigned* h = g_hist + (size_t)bg * NBINS;
    __shared__ unsigned sb[NBINS];
    __shared__ unsigned sp[256];
    int t = threadIdx.x;
    unsigned acc = 0;
    #pragma unroll 4
    for (int i = 0; i < NBINS / 256; i++) {
        unsigned v = h[t * (NBINS / 256) + i];
        sb[t * (NBINS / 256) + i] = v;
        acc += v;
    }
    sp[t] = acc;
    __syncthreads();
    if (t == 0) {
        int cum = 0, tb = 0;
        for (int c = 255; c >= 0; c--) {
            if (cum + (int)sp[c] >= TOPK) {
                int base = c * (NBINS / 256);
                for (int i = NBINS / 256 - 1; i >= 0; i--) {
                    cum += (int)sb[base + i];
                    if (cum >= TOPK) { tb = base + i; break; }
                }
                break;
            }
            cum += (int)sp[c];
        }
        g_thr[bg] = (unsigned)tb << BSHIFT;      // min float bits of threshold bin
        float m = __uint_as_float(g_maxiou[bg]);
        g_invden[bg] = (m > 0.5f) ? __fdividef(1.f, m - 0.5f) : 0.f;
    }
}

// Fused post-threshold: blocks [0,KD_CAND_BLOCKS) = candidate scan
// (block = image b x 256-anchor chunk); rest = sparse neg-loss correction.
__global__ void kD(const float4* __restrict__ br, const float4* __restrict__ anc,
                   const float4* __restrict__ tbx, const int* __restrict__ lab,
                   const float* __restrict__ logits) {
    if (blockIdx.x < KD_CAND_BLOCKS) {
        int b = blockIdx.x >> 8;
        int a = ((blockIdx.x & 255) << 8) | threadIdx.x;
        __shared__ float4 st[G];
        __shared__ float  sta[G];
        __shared__ float  sthr[G];
        if (threadIdx.x < G) {
            float4 t = tbx[b * G + threadIdx.x];
            st[threadIdx.x] = t;
            sta[threadIdx.x] = __fmul_rn(__fsub_rn(t.z, t.x), __fsub_rn(t.w, t.y));
            sthr[threadIdx.x] = __uint_as_float(g_thr[b * G + threadIdx.x]);
        }
        __syncthreads();
        Corners ac = corners_rn(anc[a]);         // hoisted: once per anchor
        #pragma unroll
        for (int g = 0; g < G; g++) {
            float4 t = st[g];
            if (!overlap_ct(ac, t)) continue;    // exact inter<=0 rejection
            float mi = iou_ct(ac, t, sta[g]);    // bit-identical to kAN's value
            // (bits>>17) >= tbin  <=>  mi >= uint_as_float(tbin<<17), both positive
            if (mi > 0.f && mi >= sthr[g]) {
                int bg = b * G + g;
                int pos = atomicAdd(&g_ccnt[bg], 1);
                if (pos < CAND) g_cand[(size_t)bg * CAND + pos] = (unsigned)a;
            }
        }
    } else {
        __shared__ float4 st[B * G];
        __shared__ float  sta[B * G];
        __shared__ float  sinv[B * G];
        __shared__ int    slbl[B * G];
        __shared__ int    sfirst[B * G];
        if (threadIdx.x < B * G) {
            float4 t = tbx[threadIdx.x];
            st[threadIdx.x] = t;
            sta[threadIdx.x] = __fmul_rn(__fsub_rn(t.z, t.x), __fsub_rn(t.w, t.y));
            sinv[threadIdx.x] = g_invden[threadIdx.x];
            slbl[threadIdx.x] = lab[threadIdx.x];
        }
        __syncthreads();
        if (threadIdx.x < B * G) {
            int b = threadIdx.x >> 4, g = threadIdx.x & 15, f = 1;
            for (int j = 0; j < g; j++) if (slbl[b * G + j] == slbl[threadIdx.x]) f = 0;
            sfirst[threadIdx.x] = f;
        }
        __syncthreads();

        int nrec = g_nrec;
        int bid = blockIdx.x - KD_CAND_BLOCKS;
        float corr = 0.f;
        for (int i = bid * blockDim.x + threadIdx.x; i < nrec; i += KD_SP_BLOCKS * blockDim.x) {
            unsigned rec = g_rec[i];
            int b = rec >> 16;
            int a = rec & 0xffff;
            float4 l = br[b * A + a];
            float4 p = anc[a];
            float dcx = p.x + l.x * 0.1f * p.z;
            float dcy = p.y + l.y * 0.1f * p.w;
            float dw  = p.z * __expf(l.z * 0.2f);
            float dh  = p.w * __expf(l.w * 0.2f);
            float dx0 = dcx - 0.5f * dw, dy0 = dcy - 0.5f * dh;
            float dx1 = dcx + 0.5f * dw, dy1 = dcy + 0.5f * dh;
            float dA  = dw * dh;
            float obp[G];
            #pragma unroll
            for (int g = 0; g < G; g++) {
                int bg = b * G + g;
                float4 t = st[bg];
                float di = 0.f;
                if ((dx0 < t.z) & (t.x < dx1) & (dy0 < t.w) & (t.y < dy1))
                    di = fiou_rn(t, sta[bg], dx0, dy0, dx1, dy1, dA);
                obp[g] = fminf(fmaxf((di - 0.5f) * sinv[bg], 0.f), 1.f);
            }
            #pragma unroll
            for (int g = 0; g < G; g++) {
                int bg = b * G + g;
                if (!sfirst[bg]) continue;
                float bp = obp[g];
                #pragma unroll
                for (int j = g + 1; j < G; j++)
                    if (slbl[b * G + j] == slbl[bg]) bp = fmaxf(bp, obp[j]);
                if (bp > 0.f) {
                    float xl = logits[((size_t)(b * A) + a) * C + slbl[bg]];
                    float pt = negterm(xl);               // cancels dense term exactly
                    float e = __expf(xl);
                    float pp = e * fastrcp(1.f + e);
                    float x = pp * (1.f - bp);
                    float xt = x * x * (-__logf(1.f - x));
                    corr += xt - pt;
                }
            }
        }
        float tot = blockReduceSum(corr);
        if (threadIdx.x == 0 && tot != 0.f) atomicAdd(&g_sums[1], (double)tot);
    }
}

// Exact top-50 select (recompute exact mqm per candidate) + positive bag loss
__global__ void kS(const float4* __restrict__ br, const float4* __restrict__ anc,
                   const float4* __restrict__ tbx, const int* __restrict__ lab,
                   const float* __restrict__ logits) {
    int bg = blockIdx.x;
    int b = bg >> 4, g = bg & 15;
    __shared__ unsigned long long skey[CAND];
    __shared__ unsigned ssel[TOPK];
    __shared__ float swv[TOPK], swl[TOPK];
    __shared__ int scount;
    float4 t = tbx[b * G + g];
    float tA = __fmul_rn(__fsub_rn(t.z, t.x), __fsub_rn(t.w, t.y));
    int cnt = min(g_ccnt[bg], CAND);
    for (int i = threadIdx.x; i < cnt; i += blockDim.x) {
        unsigned a = g_cand[(size_t)bg * CAND + i];
        Corners ac = corners_rn(anc[a]);
        float mi = iou_ct(ac, t, tA);            // bit-identical across kernels
        skey[i] = ((unsigned long long)__float_as_uint(mi) << 32) | (unsigned)(~a);
    }
    if (threadIdx.x == 0) scount = 0;
    __syncthreads();
    for (int i = threadIdx.x; i < cnt; i += blockDim.x) {
        unsigned long long k = skey[i];
        int r = 0;
        for (int j = 0; j < cnt; j++) r += (skey[j] > k);
        if (r < TOPK) {
            int s = atomicAdd(&scount, 1);
            ssel[s] = ~(unsigned)(k & 0xffffffffu);
        }
    }
    __syncthreads();
    int n = scount;
    if (threadIdx.x < n) {
        unsigned a = ssel[threadIdx.x];
        float4 p = anc[a];
        float4 l = br[(size_t)b * A + a];
        int lbl = lab[b * G + g];
        float xl = logits[((size_t)(b * A) + a) * C + lbl];
        float e = __expf(xl);
        float mcp = __fdividef(e, 1.f + e);
        float gx = __fdividef((t.x + t.z) * 0.5f - p.x, 0.1f * p.z);
        float gy = __fdividef((t.y + t.w) * 0.5f - p.y, 0.1f * p.w);
        float gw = __logf(__fdividef(t.z - t.x, p.z)) * 5.0f;
        float gh = __logf(__fdividef(t.w - t.y, p.w)) * 5.0f;
        float reg = 0.75f * (sl1(gx - l.x) + sl1(gy - l.y) + sl1(gw - l.z) + sl1(gh - l.w));
        float mbp = __expf(-reg);
        float li = mcp * mbp;
        float w = __fdividef(1.f, fmaxf(1.f - li, 1e-12f));
        swv[threadIdx.x] = w;
        swl[threadIdx.x] = w * li;
    }
    __syncthreads();
    if (threadIdx.x == 0 && n > 0) {
        float sw = 0.f, sl = 0.f;
        for (int i = 0; i < n; i++) { sw += swv[i]; sl += swl[i]; }
        float bag = __fdividef(sl, sw);
        atomicAdd(&g_sums[0], (double)(-__logf(bag)));
    }
}

__global__ void kF(float* out) {
    out[0] = (float)(g_sums[0] * (0.5 / 128.0));    // ALPHA / (B*G)
    out[1] = (float)(g_sums[1] * (0.5 / 6400.0));   // (1-ALPHA) / (B*G*TOPK)
}

// ------------------------------ launch -----------------------------------
extern "C" void kernel_launch(void* const* d_in, const int* in_sizes, int n_in,
                              void* d_out, int out_size) {
    const float4* br     = (const float4*)d_in[0];   // box_regression (B,A,4)
    const float*  logits = (const float*) d_in[1];   // cls_logits (B,A,C)
    const float4* anc    = (const float4*)d_in[2];   // anchors (A,4)
    const float4* tbx    = (const float4*)d_in[3];   // targets_boxes (B,G,4)
    const int*    lab    = (const int*)   d_in[4];   // labels (B,G)
    float* out = (float*)d_out;

    kI<<<1024, 256>>>();
    kAN<<<KA_BLOCKS + KN_BLOCKS, 256>>>(br, anc, tbx, (const float4*)logits);
    kT<<<B * G, 256>>>();
    kD<<<KD_CAND_BLOCKS + KD_SP_BLOCKS, 256>>>(br, anc, tbx, lab, logits);
    kS<<<B * G, 256>>>(br, anc, tbx, lab, logits);
    kF<<<1, 1>>>(out);
}

// round 14
// speedup vs baseline: 2.2320x; 1.0282x over previous
#include <cuda_runtime.h>

#define B 8
#define A 65536
#define C 80
#define G 16
#define TOPK 50
#define NBINS 8192
#define BSHIFT 17
#define CAND 4096
#define KA_BLOCKS 2048
#define KN_BLOCKS 6144
#define KD_CAND_BLOCKS 512          // 128 bg x 4 chunks
#define KD_SP_BLOCKS 256

// ------------------------- static device scratch -------------------------
__device__ unsigned g_hist[(size_t)B * G * NBINS];     // 4.2 MB histograms
__device__ unsigned g_maxiou[B * G];                   // max decoded IoU (bits)
__device__ int      g_tbin[B * G];                     // threshold bin
__device__ float    g_invden[B * G];                   // 1/(t2-0.5) or 0
__device__ int      g_ccnt[B * G];                     // candidate counts
__device__ unsigned g_cand[(size_t)B * G * CAND];      // candidate anchor ids
__device__ unsigned short g_mbin[(size_t)B * G * A];   // 16.8 MB mqm bins+1 (0 = no overlap)
__device__ int      g_nrec;                            // sparse record count
__device__ unsigned g_rec[B * A];                      // sparse records (b<<16 | a)
__device__ double   g_sums[2];                         // [0]=pos, [1]=neg

// ------------------------------ helpers ---------------------------------
// _rn-pinned ops: all IoU computations are bitwise identical across call sites.
struct Corners { float x0, y0, x1, y1, area; };

__device__ __forceinline__ Corners corners_rn(const float4 p) {
    Corners c;
    c.x0 = __fmaf_rn(-0.5f, p.z, p.x);
    c.y0 = __fmaf_rn(-0.5f, p.w, p.y);
    c.x1 = __fmaf_rn( 0.5f, p.z, p.x);
    c.y1 = __fmaf_rn( 0.5f, p.w, p.y);
    c.area = __fmul_rn(p.z, p.w);
    return c;
}

__device__ __forceinline__ float iou_ct(const Corners c, const float4 t, float tA) {
    float iw = fmaxf(__fsub_rn(fminf(c.x1, t.z), fmaxf(c.x0, t.x)), 0.f);
    float ih = fmaxf(__fsub_rn(fminf(c.y1, t.w), fmaxf(c.y0, t.y)), 0.f);
    float inter = __fmul_rn(iw, ih);
    if (inter <= 0.f) return 0.f;
    return __fdividef(inter, __fsub_rn(__fadd_rn(tA, c.area), inter));
}

__device__ __forceinline__ float fiou_rn(const float4 t, float tA,
                                         float bx0, float by0, float bx1, float by1, float bA) {
    float iw = fmaxf(__fsub_rn(fminf(t.z, bx1), fmaxf(t.x, bx0)), 0.f);
    float ih = fmaxf(__fsub_rn(fminf(t.w, by1), fmaxf(t.y, by0)), 0.f);
    float inter = __fmul_rn(iw, ih);
    if (inter <= 0.f) return 0.f;
    return __fdividef(inter, __fsub_rn(__fadd_rn(tA, bA), inter));
}

__device__ __forceinline__ float fastrcp(float s) {
    float r = __uint_as_float(0x7EF311C3u - __float_as_uint(s));
    r = r * (2.f - s * r);
    r = r * (2.f - s * r);
    r = r * (2.f - s * r);
    return r;
}

// sigmoid(x)^2 * softplus(x): 2 MUFU (EX2 + LG2)
__device__ __forceinline__ float negterm(float x) {
    float e = __expf(x);
    float s = 1.f + e;
    float p = e * fastrcp(s);
    return p * p * __logf(s);
}

__device__ __forceinline__ float sl1(float v) {
    float av = fabsf(v);
    return (av < 0.11f) ? 4.5454545454545450f * v * v : av - 0.055f;
}

__device__ __forceinline__ float blockReduceSum(float v) {
    __shared__ float s[32];
    int lane = threadIdx.x & 31, wid = threadIdx.x >> 5;
    #pragma unroll
    for (int o = 16; o; o >>= 1) v += __shfl_down_sync(0xffffffffu, v, o);
    if (lane == 0) s[wid] = v;
    __syncthreads();
    int nw = (blockDim.x + 31) >> 5;
    v = (threadIdx.x < nw) ? s[threadIdx.x] : 0.f;
    if (wid == 0) {
        #pragma unroll
        for (int o = 16; o; o >>= 1) v += __shfl_down_sync(0xffffffffu, v, o);
    }
    return v; // valid in thread 0
}

// ------------------------------ kernels ---------------------------------
__global__ void kI() {
    size_t i = (size_t)blockIdx.x * blockDim.x + threadIdx.x;
    uint4* h4 = (uint4*)g_hist;
    const size_t n4 = (size_t)B * G * NBINS / 4;
    if (i < n4) h4[i] = make_uint4(0u, 0u, 0u, 0u);
    if (i < B * G) { g_maxiou[i] = 0u; g_ccnt[i] = 0; }
    if (i == 0) { g_sums[0] = 0.0; g_sums[1] = 0.0; g_nrec = 0; }
}

// Fused: blocks [0,KA_BLOCKS) = per-anchor pass (hist + bin store + t2 max +
//        sparse records); rest = dense negative loss over logits.
__global__ void kAN(const float4* __restrict__ br, const float4* __restrict__ anc,
                    const float4* __restrict__ tbx, const float4* __restrict__ logits4) {
    if (blockIdx.x < KA_BLOCKS) {
        int b = blockIdx.x >> 8;
        int a = ((blockIdx.x & 255) << 8) | threadIdx.x;
        __shared__ float4 st[G];
        __shared__ float  sta[G];
        __shared__ unsigned smax[G];
        if (threadIdx.x < G) {
            float4 t = tbx[b * G + threadIdx.x];
            st[threadIdx.x] = t;
            sta[threadIdx.x] = __fmul_rn(__fsub_rn(t.z, t.x), __fsub_rn(t.w, t.y));
            smax[threadIdx.x] = 0u;
        }
        __syncthreads();

        float4 l = br[b * A + a];
        float4 p = anc[a];
        Corners ac = corners_rn(p);
        float dcx = p.x + l.x * 0.1f * p.z;
        float dcy = p.y + l.y * 0.1f * p.w;
        float dw  = p.z * __expf(l.z * 0.2f);
        float dh  = p.w * __expf(l.w * 0.2f);
        float dx0 = dcx - 0.5f * dw, dy0 = dcy - 0.5f * dh;
        float dx1 = dcx + 0.5f * dw, dy1 = dcy + 0.5f * dh;
        float dA  = dw * dh;

        size_t hbase = (size_t)(b * G) * NBINS;
        float dmax = 0.f;
        #pragma unroll
        for (int g = 0; g < G; g++) {
            float4 t = st[g];
            // mqm IoU: histogram + persisted bin (the ONLY full-grid mqm compute)
            float mi = iou_ct(ac, t, sta[g]);
            unsigned bin1 = 0u;
            if (mi > 0.f) {
                unsigned bin = __float_as_uint(mi) >> BSHIFT;
                bin1 = bin + 1u;
                atomicAdd(&g_hist[hbase + (size_t)g * NBINS + bin], 1u);
            }
            g_mbin[(size_t)(b * G + g) * A + a] = (unsigned short)bin1;
            // decoded IoU: t2 max
            float di = fiou_rn(t, sta[g], dx0, dy0, dx1, dy1, dA);
            dmax = fmaxf(dmax, di);
            unsigned db = __float_as_uint(di);
            if (db > smax[g]) atomicMax(&smax[g], db);   // read-filtered max
        }
        if (dmax > 0.49f) {                      // margin vs recompute drift
            int pos = atomicAdd(&g_nrec, 1);
            g_rec[pos] = ((unsigned)b << 16) | (unsigned)a;
        }
        __syncthreads();
        if (threadIdx.x < G) atomicMax(&g_maxiou[b * G + threadIdx.x], smax[threadIdx.x]);
    } else {
        const int n4 = B * A * C / 4;
        int bid = blockIdx.x - KA_BLOCKS;
        float acc = 0.f;
        for (int i = bid * blockDim.x + threadIdx.x; i < n4; i += KN_BLOCKS * blockDim.x) {
            float4 v = logits4[i];
            acc += negterm(v.x) + negterm(v.y) + negterm(v.z) + negterm(v.w);
        }
        float tot = blockReduceSum(acc);
        if (threadIdx.x == 0) atomicAdd(&g_sums[1], (double)tot);
    }
}

// Threshold per (b,g): largest suffix bin with count >= TOPK; invden
__global__ void kT() {
    int bg = blockIdx.x;
    const unsigned* h = g_hist + (size_t)bg * NBINS;
    __shared__ unsigned sb[NBINS];
    __shared__ unsigned sp[256];
    int t = threadIdx.x;
    unsigned acc = 0;
    #pragma unroll 4
    for (int i = 0; i < NBINS / 256; i++) {
        unsigned v = h[t * (NBINS / 256) + i];
        sb[t * (NBINS / 256) + i] = v;
        acc += v;
    }
    sp[t] = acc;
    __syncthreads();
    if (t == 0) {
        int cum = 0, tb = 0;
        for (int c = 255; c >= 0; c--) {
            if (cum + (int)sp[c] >= TOPK) {
                int base = c * (NBINS / 256);
                for (int i = NBINS / 256 - 1; i >= 0; i--) {
                    cum += (int)sb[base + i];
                    if (cum >= TOPK) { tb = base + i; break; }
                }
                break;
            }
            cum += (int)sp[c];
        }
        g_tbin[bg] = tb;
        float m = __uint_as_float(g_maxiou[bg]);
        g_invden[bg] = (m > 0.5f) ? __fdividef(1.f, m - 0.5f) : 0.f;
    }
}

// Fused post-threshold:
//  blocks [0,KD_CAND_BLOCKS): pure-bandwidth candidate scan of stored bins
//   (block = bg x quarter; each thread: uint4 loads = 8 packed u16 bins)
//  rest: sparse neg-loss correction.
__global__ void kD(const float4* __restrict__ br, const float4* __restrict__ anc,
                   const float4* __restrict__ tbx, const int* __restrict__ lab,
                   const float* __restrict__ logits) {
    if (blockIdx.x < KD_CAND_BLOCKS) {
        int bg = blockIdx.x >> 2;
        int chunk = blockIdx.x & 3;
        unsigned tb1 = (unsigned)g_tbin[bg] + 1u;  // stored bins are bin+1
        const uint4* mb = (const uint4*)(g_mbin + (size_t)bg * A + chunk * (A / 4));
        // A/4 = 16384 anchors per chunk; 8 anchors per uint4 -> 2048 uint4 / 256 thr = 8 iters
        #pragma unroll
        for (int i = 0; i < 8; i++) {
            int idx = i * 256 + threadIdx.x;
            uint4 v = mb[idx];
            int abase = chunk * (A / 4) + idx * 8;
            unsigned w[4] = { v.x, v.y, v.z, v.w };
            #pragma unroll
            for (int j = 0; j < 4; j++) {
                unsigned lo = w[j] & 0xffffu, hi = w[j] >> 16;
                if (lo >= tb1) {
                    int pos = atomicAdd(&g_ccnt[bg], 1);
                    if (pos < CAND) g_cand[(size_t)bg * CAND + pos] = (unsigned)(abase + 2 * j);
                }
                if (hi >= tb1) {
                    int pos = atomicAdd(&g_ccnt[bg], 1);
                    if (pos < CAND) g_cand[(size_t)bg * CAND + pos] = (unsigned)(abase + 2 * j + 1);
                }
            }
        }
    } else {
        __shared__ float4 st[B * G];
        __shared__ float  sta[B * G];
        __shared__ float  sinv[B * G];
        __shared__ int    slbl[B * G];
        __shared__ int    sfirst[B * G];
        if (threadIdx.x < B * G) {
            float4 t = tbx[threadIdx.x];
            st[threadIdx.x] = t;
            sta[threadIdx.x] = __fmul_rn(__fsub_rn(t.z, t.x), __fsub_rn(t.w, t.y));
            sinv[threadIdx.x] = g_invden[threadIdx.x];
            slbl[threadIdx.x] = lab[threadIdx.x];
        }
        __syncthreads();
        if (threadIdx.x < B * G) {
            int b = threadIdx.x >> 4, g = threadIdx.x & 15, f = 1;
            for (int j = 0; j < g; j++) if (slbl[b * G + j] == slbl[threadIdx.x]) f = 0;
            sfirst[threadIdx.x] = f;
        }
        __syncthreads();

        int nrec = g_nrec;
        int bid = blockIdx.x - KD_CAND_BLOCKS;
        float corr = 0.f;
        for (int i = bid * blockDim.x + threadIdx.x; i < nrec; i += KD_SP_BLOCKS * blockDim.x) {
            unsigned rec = g_rec[i];
            int b = rec >> 16;
            int a = rec & 0xffff;
            float4 l = br[b * A + a];
            float4 p = anc[a];
            float dcx = p.x + l.x * 0.1f * p.z;
            float dcy = p.y + l.y * 0.1f * p.w;
            float dw  = p.z * __expf(l.z * 0.2f);
            float dh  = p.w * __expf(l.w * 0.2f);
            float dx0 = dcx - 0.5f * dw, dy0 = dcy - 0.5f * dh;
            float dx1 = dcx + 0.5f * dw, dy1 = dcy + 0.5f * dh;
            float dA  = dw * dh;
            float obp[G];
            #pragma unroll
            for (int g = 0; g < G; g++) {
                int bg = b * G + g;
                float di = fiou_rn(st[bg], sta[bg], dx0, dy0, dx1, dy1, dA);
                obp[g] = fminf(fmaxf((di - 0.5f) * sinv[bg], 0.f), 1.f);
            }
            #pragma unroll
            for (int g = 0; g < G; g++) {
                int bg = b * G + g;
                if (!sfirst[bg]) continue;
                float bp = obp[g];
                #pragma unroll
                for (int j = g + 1; j < G; j++)
                    if (slbl[b * G + j] == slbl[bg]) bp = fmaxf(bp, obp[j]);
                if (bp > 0.f) {
                    float xl = logits[((size_t)(b * A) + a) * C + slbl[bg]];
                    float pt = negterm(xl);               // cancels dense term exactly
                    float e = __expf(xl);
                    float pp = e * fastrcp(1.f + e);
                    float x = pp * (1.f - bp);
                    float xt = x * x * (-__logf(1.f - x));
                    corr += xt - pt;
                }
            }
        }
        float tot = blockReduceSum(corr);
        if (threadIdx.x == 0 && tot != 0.f) atomicAdd(&g_sums[1], (double)tot);
    }
}

// Exact top-50 select (recompute exact mqm per candidate) + positive bag loss
__global__ void kS(const float4* __restrict__ br, const float4* __restrict__ anc,
                   const float4* __restrict__ tbx, const int* __restrict__ lab,
                   const float* __restrict__ logits) {
    int bg = blockIdx.x;
    int b = bg >> 4, g = bg & 15;
    __shared__ unsigned long long skey[CAND];
    __shared__ unsigned ssel[TOPK];
    __shared__ float swv[TOPK], swl[TOPK];
    __shared__ int scount;
    float4 t = tbx[b * G + g];
    float tA = __fmul_rn(__fsub_rn(t.z, t.x), __fsub_rn(t.w, t.y));
    int cnt = min(g_ccnt[bg], CAND);
    for (int i = threadIdx.x; i < cnt; i += blockDim.x) {
        unsigned a = g_cand[(size_t)bg * CAND + i];
        Corners ac = corners_rn(anc[a]);
        float mi = iou_ct(ac, t, tA);            // bit-identical across kernels
        skey[i] = ((unsigned long long)__float_as_uint(mi) << 32) | (unsigned)(~a);
    }
    if (threadIdx.x == 0) scount = 0;
    __syncthreads();
    for (int i = threadIdx.x; i < cnt; i += blockDim.x) {
        unsigned long long k = skey[i];
        int r = 0;
        for (int j = 0; j < cnt; j++) r += (skey[j] > k);
        if (r < TOPK) {
            int s = atomicAdd(&scount, 1);
            ssel[s] = ~(unsigned)(k & 0xffffffffu);
        }
    }
    __syncthreads();
    int n = scount;
    if (threadIdx.x < n) {
        unsigned a = ssel[threadIdx.x];
        float4 p = anc[a];
        float4 l = br[(size_t)b * A + a];
        int lbl = lab[b * G + g];
        float xl = logits[((size_t)(b * A) + a) * C + lbl];
        float e = __expf(xl);
        float mcp = __fdividef(e, 1.f + e);
        float gx = __fdividef((t.x + t.z) * 0.5f - p.x, 0.1f * p.z);
        float gy = __fdividef((t.y + t.w) * 0.5f - p.y, 0.1f * p.w);
        float gw = __logf(__fdividef(t.z - t.x, p.z)) * 5.0f;
        float gh = __logf(__fdividef(t.w - t.y, p.w)) * 5.0f;
        float reg = 0.75f * (sl1(gx - l.x) + sl1(gy - l.y) + sl1(gw - l.z) + sl1(gh - l.w));
        float mbp = __expf(-reg);
        float li = mcp * mbp;
        float w = __fdividef(1.f, fmaxf(1.f - li, 1e-12f));
        swv[threadIdx.x] = w;
        swl[threadIdx.x] = w * li;
    }
    __syncthreads();
    if (threadIdx.x == 0 && n > 0) {
        float sw = 0.f, sl = 0.f;
        for (int i = 0; i < n; i++) { sw += swv[i]; sl += swl[i]; }
        float bag = __fdividef(sl, sw);
        atomicAdd(&g_sums[0], (double)(-__logf(bag)));
    }
}

__global__ void kF(float* out) {
    out[0] = (float)(g_sums[0] * (0.5 / 128.0));    // ALPHA / (B*G)
    out[1] = (float)(g_sums[1] * (0.5 / 6400.0));   // (1-ALPHA) / (B*G*TOPK)
}

// ------------------------------ launch -----------------------------------
extern "C" void kernel_launch(void* const* d_in, const int* in_sizes, int n_in,
                              void* d_out, int out_size) {
    const float4* br     = (const float4*)d_in[0];   // box_regression (B,A,4)
    const float*  logits = (const float*) d_in[1];   // cls_logits (B,A,C)
    const float4* anc    = (const float4*)d_in[2];   // anchors (A,4)
    const float4* tbx    = (const float4*)d_in[3];   // targets_boxes (B,G,4)
    const int*    lab    = (const int*)   d_in[4];   // labels (B,G)
    float* out = (float*)d_out;

    kI<<<1024, 256>>>();
    kAN<<<KA_BLOCKS + KN_BLOCKS, 256>>>(br, anc, tbx, (const float4*)logits);
    kT<<<B * G, 256>>>();
    kD<<<KD_CAND_BLOCKS + KD_SP_BLOCKS, 256>>>(br, anc, tbx, lab, logits);
    kS<<<B * G, 256>>>(br, anc, tbx, lab, logits);
    kF<<<1, 1>>>(out);
}